// round 2
// baseline (speedup 1.0000x reference)
#include <cuda_runtime.h>
#include <math.h>

typedef unsigned long long u64;
#define DEV __device__ __forceinline__

constexpr int B = 4, TH = 120, STEPS = 8, D_IN = 32, D_MODEL = 512;
constexpr int N_HEADS = 8, N_LAYERS = 4, D_FF = 2048, N_SUB = 5;
constexpr int T = 128;          // TH + STEPS
constexpr int M = 512;          // B * T
constexpr float LN_EPS = 1e-5f;
constexpr float NEGMIN = -3.402823466e38f;
constexpr float EMB_SCALE = 22.627416997969522f;   // sqrt(512)
constexpr float INV_SQRT_DH = 0.125f;              // 1/sqrt(64)

// -------- device scratch (no allocations allowed) --------
__device__ float g_buf[B][T][D_IN];
__device__ float g_h[M][D_MODEL];
__device__ float g_q[M][D_MODEL];
__device__ float g_k[M][D_MODEL];
__device__ float g_v[M][D_MODEL];
__device__ float g_attn[M][D_MODEL];
__device__ float g_tmp[M][D_MODEL];
__device__ float g_ff[M][D_FF];
__device__ float g_cur[B][D_IN];
__device__ float g_ffr[B][D_FF];

// -------- packed f32x2 helpers (bitwise == scalar FFMA) --------
DEV u64 pack2(float lo, float hi) {
    u64 r; asm("mov.b64 %0, {%1, %2};" : "=l"(r) : "f"(lo), "f"(hi)); return r;
}
DEV float2 unpack2(u64 v) {
    float2 r; asm("mov.b64 {%0, %1}, %2;" : "=f"(r.x), "=f"(r.y) : "l"(v)); return r;
}
DEV void fma2(u64& c, u64 a, u64 b) {
    asm("fma.rn.f32x2 %0, %1, %2, %0;" : "+l"(c) : "l"(a), "l"(b));
}
union F4U { float4 f; u64 u[2]; };

DEV float gelu(float x) {
    return 0.5f * x * (1.0f + tanhf(0.7978845608028654f * (x + 0.044715f * x * x * x)));
}

// =============== buf init (every replay; deterministic) ===============
__global__ void init_buf_kernel(const float* __restrict__ history) {
    int b = blockIdx.x;
    for (int idx = threadIdx.x; idx < T * D_IN; idx += blockDim.x) {
        int t = idx >> 5, i = idx & 31;
        g_buf[b][t][i] = (t < TH) ? history[(b * TH + t) * D_IN + i] : 0.0f;
    }
}

// =============== embedding + positional encoding ===============
__global__ void embed_kernel(const float* __restrict__ Wemb,
                             const float* __restrict__ bemb) {
    int row = blockIdx.x;              // b*T + t
    int t = row & (T - 1);
    int b = row >> 7;
    __shared__ float xs[D_IN];
    int tid = threadIdx.x;             // 128
    if (tid < D_IN) xs[tid] = g_buf[b][t][tid];
    __syncthreads();
#pragma unroll
    for (int c = 0; c < 4; c++) {
        int d = tid + c * 128;
        const float* w = Wemb + d * D_IN;
        float s = 0.0f;
#pragma unroll
        for (int i = 0; i < D_IN; i += 4) {
            float4 wv = *(const float4*)&w[i];
            s += wv.x * xs[i] + wv.y * xs[i + 1] + wv.z * xs[i + 2] + wv.w * xs[i + 3];
        }
        s = (s + bemb[d]) * EMB_SCALE;
        int j2 = d & ~1;
        float ang = (float)t * expf((float)j2 * (-9.210340371976184f / 512.0f));
        s += (d & 1) ? cosf(ang) : sinf(ang);
        g_h[row][d] = s;
    }
}

// =============== GEMM: C[M,N] = A[M,K] @ W[N,K]^T (+ epilogue) ===============
// EPI: 0 none | 1 gelu(c+bias) | 2 c+res | 3 c+bias+res
template <int EPI>
__global__ void __launch_bounds__(256) gemm_kernel(
    const float* __restrict__ A,
    const float* __restrict__ W0, const float* __restrict__ W1p,
    const float* __restrict__ W2p,
    float* __restrict__ O0, float* __restrict__ O1, float* __restrict__ O2,
    const float* __restrict__ bias, const float* __restrict__ res,
    int N, int K) {
    const float* __restrict__ W = blockIdx.z == 0 ? W0 : (blockIdx.z == 1 ? W1p : W2p);
    float* __restrict__ O = blockIdx.z == 0 ? O0 : (blockIdx.z == 1 ? O1 : O2);

    __shared__ float As[16][68];
    __shared__ float Ws[16][68];

    int tid = threadIdx.x;
    int tx = tid & 15, ty = tid >> 4;
    int m0 = blockIdx.y * 64, n0 = blockIdx.x * 64;
    int lm = tid >> 2, kq = tid & 3;

    u64 zero2 = pack2(0.0f, 0.0f);
    u64 acc[4][2];
#pragma unroll
    for (int i = 0; i < 4; i++) { acc[i][0] = zero2; acc[i][1] = zero2; }

    const float* Ap = &A[(m0 + lm) * K + kq * 4];
    const float* Wp = &W[(n0 + lm) * K + kq * 4];
    F4U av, wv;
    av.f = *(const float4*)Ap;
    wv.f = *(const float4*)Wp;

    for (int kt = 0; kt < K; kt += 16) {
        As[kq * 4 + 0][lm] = av.f.x; As[kq * 4 + 1][lm] = av.f.y;
        As[kq * 4 + 2][lm] = av.f.z; As[kq * 4 + 3][lm] = av.f.w;
        Ws[kq * 4 + 0][lm] = wv.f.x; Ws[kq * 4 + 1][lm] = wv.f.y;
        Ws[kq * 4 + 2][lm] = wv.f.z; Ws[kq * 4 + 3][lm] = wv.f.w;
        __syncthreads();
        if (kt + 16 < K) {
            av.f = *(const float4*)(Ap + kt + 16);
            wv.f = *(const float4*)(Wp + kt + 16);
        }
#pragma unroll
        for (int kk = 0; kk < 16; kk++) {
            F4U wr; wr.f = *(const float4*)&Ws[kk][tx * 4];
            F4U ar; ar.f = *(const float4*)&As[kk][ty * 4];
            float a4[4] = {ar.f.x, ar.f.y, ar.f.z, ar.f.w};
#pragma unroll
            for (int i = 0; i < 4; i++) {
                u64 a2 = pack2(a4[i], a4[i]);
                fma2(acc[i][0], a2, wr.u[0]);
                fma2(acc[i][1], a2, wr.u[1]);
            }
        }
        __syncthreads();
    }

    int col = n0 + tx * 4;
#pragma unroll
    for (int i = 0; i < 4; i++) {
        int row = m0 + ty * 4 + i;
        float2 c01 = unpack2(acc[i][0]);
        float2 c23 = unpack2(acc[i][1]);
        float c[4] = {c01.x, c01.y, c23.x, c23.y};
        if (EPI == 1) {
#pragma unroll
            for (int j = 0; j < 4; j++) c[j] = gelu(c[j] + bias[col + j]);
        } else if (EPI == 2) {
            const float4 r4 = *(const float4*)&res[row * N + col];
            c[0] += r4.x; c[1] += r4.y; c[2] += r4.z; c[3] += r4.w;
        } else if (EPI == 3) {
            const float4 r4 = *(const float4*)&res[row * N + col];
            const float4 b4 = *(const float4*)&bias[col];
            c[0] += r4.x + b4.x; c[1] += r4.y + b4.y;
            c[2] += r4.z + b4.z; c[3] += r4.w + b4.w;
        }
        float4 o4 = {c[0], c[1], c[2], c[3]};
        *(float4*)&O[row * N + col] = o4;
    }
}

// =============== LayerNorm (row-wise, D=512) ===============
__global__ void ln_kernel(const float* __restrict__ X,
                          const float* __restrict__ gam,
                          const float* __restrict__ bet,
                          float* __restrict__ O) {
    int row = blockIdx.x;
    int tid = threadIdx.x;   // 128
    __shared__ float red[4];
    float4 x = *(const float4*)&X[row * 512 + tid * 4];
    float s = x.x + x.y + x.z + x.w;
#pragma unroll
    for (int o = 16; o; o >>= 1) s += __shfl_xor_sync(~0u, s, o);
    if ((tid & 31) == 0) red[tid >> 5] = s;
    __syncthreads();
    float mu = (red[0] + red[1] + red[2] + red[3]) * (1.0f / 512.0f);
    float dx = x.x - mu, dy = x.y - mu, dz = x.z - mu, dw = x.w - mu;
    float v = dx * dx + dy * dy + dz * dz + dw * dw;
#pragma unroll
    for (int o = 16; o; o >>= 1) v += __shfl_xor_sync(~0u, v, o);
    __syncthreads();
    if ((tid & 31) == 0) red[tid >> 5] = v;
    __syncthreads();
    float var = (red[0] + red[1] + red[2] + red[3]) * (1.0f / 512.0f);
    float inv = 1.0f / sqrtf(var + LN_EPS);
    int c = tid * 4;
    float4 o4;
    o4.x = dx * inv * gam[c + 0] + bet[c + 0];
    o4.y = dy * inv * gam[c + 1] + bet[c + 1];
    o4.z = dz * inv * gam[c + 2] + bet[c + 2];
    o4.w = dw * inv * gam[c + 3] + bet[c + 3];
    *(float4*)&O[row * 512 + c] = o4;
}

// =============== Attention: block = (q-tile of 32) x (b,h) ===============
// mask: attend where key index > query index (anti-causal, faithful to source)
__global__ void __launch_bounds__(128) attn_kernel() {
    __shared__ float KV[64][64];
    __shared__ float Ls[32][132];   // padded: kills 8-way bank conflict
    int qt = blockIdx.x, bh = blockIdx.y;
    int b = bh >> 3, h = bh & 7;
    int tid = threadIdx.x;
    int qr = tid >> 2, dg = tid & 3, d0 = dg * 16;
    int qi = qt * 32 + qr;
    int base = b * T;
    int hc = h * 64;

    F4U q[4];
#pragma unroll
    for (int j = 0; j < 4; j++)
        q[j].f = *(const float4*)&g_q[base + qi][hc + d0 + j * 4];

    float m = NEGMIN;
    // ---- pass 1: logits ----
    for (int kc = 0; kc < 128; kc += 64) {
        for (int idx = tid; idx < 64 * 16; idx += 128) {
            int r = idx >> 4, c = idx & 15;
            *(float4*)&KV[r][c * 4] = *(const float4*)&g_k[base + kc + r][hc + c * 4];
        }
        __syncthreads();
        for (int k = 0; k < 64; k++) {
            u64 a0 = pack2(0.0f, 0.0f), a1 = pack2(0.0f, 0.0f);
#pragma unroll
            for (int j = 0; j < 4; j++) {
                F4U kv; kv.f = *(const float4*)&KV[k][d0 + j * 4];
                fma2(a0, q[j].u[0], kv.u[0]);
                fma2(a1, q[j].u[1], kv.u[1]);
            }
            float2 p0 = unpack2(a0), p1 = unpack2(a1);
            float s = p0.x + p0.y + p1.x + p1.y;
            s += __shfl_xor_sync(~0u, s, 1);
            s += __shfl_xor_sync(~0u, s, 2);
            int kg = kc + k;
            s = (kg > qi) ? s * INV_SQRT_DH : NEGMIN;
            m = fmaxf(m, s);
            if ((kg >> 5) == dg) Ls[qr][kg] = s;
        }
        __syncthreads();
    }
    // ---- softmax weights (single exp per logit) ----
    float lp = 0.0f;
#pragma unroll
    for (int j = 0; j < 32; j++) {
        int kg = dg * 32 + j;
        float p = expf(Ls[qr][kg] - m);
        Ls[qr][kg] = p;
        lp += p;
    }
    lp += __shfl_xor_sync(~0u, lp, 1);
    lp += __shfl_xor_sync(~0u, lp, 2);
    __syncthreads();
    // ---- pass 2: weighted V ----
    F4U o[4];
#pragma unroll
    for (int j = 0; j < 4; j++) { o[j].u[0] = pack2(0.f, 0.f); o[j].u[1] = pack2(0.f, 0.f); }
    for (int kc = 0; kc < 128; kc += 64) {
        for (int idx = tid; idx < 64 * 16; idx += 128) {
            int r = idx >> 4, c = idx & 15;
            *(float4*)&KV[r][c * 4] = *(const float4*)&g_v[base + kc + r][hc + c * 4];
        }
        __syncthreads();
        for (int k = 0; k < 64; k++) {
            float p = Ls[qr][kc + k];
            u64 p2 = pack2(p, p);
#pragma unroll
            for (int j = 0; j < 4; j++) {
                F4U vv; vv.f = *(const float4*)&KV[k][d0 + j * 4];
                fma2(o[j].u[0], p2, vv.u[0]);
                fma2(o[j].u[1], p2, vv.u[1]);
            }
        }
        __syncthreads();
    }
    float invl = 1.0f / lp;
#pragma unroll
    for (int j = 0; j < 4; j++) {
        float4 r4;
        r4.x = o[j].f.x * invl; r4.y = o[j].f.y * invl;
        r4.z = o[j].f.z * invl; r4.w = o[j].f.w * invl;
        *(float4*)&g_attn[base + qi][hc + d0 + j * 4] = r4;
    }
}

// =============== refine head, stage A: comb -> ff (2048 rows) ===============
__global__ void __launch_bounds__(256) refineA_kernel(
    const float* __restrict__ Wemb, const float* __restrict__ bemb,
    const float* __restrict__ Wr1, const float* __restrict__ br1,
    int step, int first) {
    int b = blockIdx.x >> 4, part = blockIdx.x & 15;
    __shared__ float comb[1024];
    __shared__ float cur[32];
    int tid = threadIdx.x;
    int ptr = TH + step;
    if (tid < 32) cur[tid] = first ? g_buf[b][ptr - 1][tid] : g_cur[b][tid];
    __syncthreads();
    for (int d = tid; d < 512; d += 256) {
        const float* w = &Wemb[d * 32];
        float s = 0.0f;
#pragma unroll
        for (int i = 0; i < 32; i += 4) {
            float4 wv = *(const float4*)&w[i];
            s += wv.x * cur[i] + wv.y * cur[i + 1] + wv.z * cur[i + 2] + wv.w * cur[i + 3];
        }
        comb[d] = (s + bemb[d]) * EMB_SCALE;
    }
    for (int d = tid; d < 512; d += 256) comb[512 + d] = g_h[b * T + ptr - 1][d];
    __syncthreads();

    int r = part * 128 + (tid >> 1);
    int half = tid & 1;
    const float* w = &Wr1[r * 1024 + half * 512];
    const float* cb = &comb[half * 512];
    u64 a0 = pack2(0.f, 0.f), a1 = pack2(0.f, 0.f);
    for (int i = 0; i < 512; i += 4) {
        F4U wv; wv.f = *(const float4*)&w[i];
        F4U cv; cv.f = *(const float4*)&cb[i];
        fma2(a0, wv.u[0], cv.u[0]);
        fma2(a1, wv.u[1], cv.u[1]);
    }
    float2 x0 = unpack2(a0), x1 = unpack2(a1);
    float s = x0.x + x0.y + x1.x + x1.y;
    s += __shfl_xor_sync(~0u, s, 1);
    if (half == 0) g_ffr[b][r] = gelu(s + br1[r]);
}

// =============== refine head, stage B: delta + cur update ===============
__global__ void __launch_bounds__(256) refineB_kernel(
    const float* __restrict__ Wr2, const float* __restrict__ br2,
    float* __restrict__ out, int step, int first, int last) {
    int b = blockIdx.x;
    int tid = threadIdx.x;
    __shared__ float ff[2048];
    for (int i = tid; i < 2048; i += 256) ff[i] = g_ffr[b][i];
    __syncthreads();
    int i = tid >> 3, part = tid & 7;
    const float* w = &Wr2[i * 2048 + part * 256];
    const float* f = &ff[part * 256];
    u64 a0 = pack2(0.f, 0.f), a1 = pack2(0.f, 0.f);
    for (int j = 0; j < 256; j += 4) {
        F4U wv; wv.f = *(const float4*)&w[j];
        F4U fv; fv.f = *(const float4*)&f[j];
        fma2(a0, wv.u[0], fv.u[0]);
        fma2(a1, wv.u[1], fv.u[1]);
    }
    float2 x0 = unpack2(a0), x1 = unpack2(a1);
    float s = x0.x + x0.y + x1.x + x1.y;
    s += __shfl_xor_sync(~0u, s, 1);
    s += __shfl_xor_sync(~0u, s, 2);
    s += __shfl_xor_sync(~0u, s, 4);
    if (part == 0) {
        int ptr = TH + step;
        float base = first ? g_buf[b][ptr - 1][i] : g_cur[b][i];
        float nv = base + s + br2[i];
        g_cur[b][i] = nv;
        if (last) {
            g_buf[b][ptr][i] = nv;
            out[(b * STEPS + step) * D_IN + i] = nv;
        }
    }
}

// =============== host orchestration ===============
extern "C" void kernel_launch(void* const* d_in, const int* in_sizes, int n_in,
                              void* d_out, int out_size) {
    int o = (n_in >= 20) ? 1 : 0;   // "steps" scalar occupies index 1 if present
    const float* history = (const float*)d_in[0];
    const float* Wemb = (const float*)d_in[1 + o];
    const float* bemb = (const float*)d_in[2 + o];
    const float* Wq = (const float*)d_in[3 + o];
    const float* Wk = (const float*)d_in[4 + o];
    const float* Wv = (const float*)d_in[5 + o];
    const float* Wo = (const float*)d_in[6 + o];
    const float* ln1g = (const float*)d_in[7 + o];
    const float* ln1b = (const float*)d_in[8 + o];
    const float* W1 = (const float*)d_in[9 + o];
    const float* b1 = (const float*)d_in[10 + o];
    const float* W2 = (const float*)d_in[11 + o];
    const float* b2 = (const float*)d_in[12 + o];
    const float* ln2g = (const float*)d_in[13 + o];
    const float* ln2b = (const float*)d_in[14 + o];
    const float* Wr1 = (const float*)d_in[15 + o];
    const float* br1 = (const float*)d_in[16 + o];
    const float* Wr2 = (const float*)d_in[17 + o];
    const float* br2 = (const float*)d_in[18 + o];
    float* out = (float*)d_out;

    void* p;
    cudaGetSymbolAddress(&p, g_h);    float* ph = (float*)p;
    cudaGetSymbolAddress(&p, g_q);    float* pq = (float*)p;
    cudaGetSymbolAddress(&p, g_k);    float* pk = (float*)p;
    cudaGetSymbolAddress(&p, g_v);    float* pv = (float*)p;
    cudaGetSymbolAddress(&p, g_attn); float* pat = (float*)p;
    cudaGetSymbolAddress(&p, g_tmp);  float* ptmp = (float*)p;
    cudaGetSymbolAddress(&p, g_ff);   float* pff = (float*)p;

    init_buf_kernel<<<B, 256>>>(history);

    for (int step = 0; step < STEPS; step++) {
        embed_kernel<<<M, 128>>>(Wemb, bemb);
        for (int l = 0; l < N_LAYERS; l++) {
            const float* wq = Wq + l * D_MODEL * D_MODEL;
            const float* wk = Wk + l * D_MODEL * D_MODEL;
            const float* wv = Wv + l * D_MODEL * D_MODEL;
            const float* wo = Wo + l * D_MODEL * D_MODEL;
            const float* w1 = W1 + l * D_FF * D_MODEL;
            const float* w2 = W2 + l * D_MODEL * D_FF;

            gemm_kernel<0><<<dim3(8, 8, 3), 256>>>(ph, wq, wk, wv, pq, pk, pv,
                                                   nullptr, nullptr, 512, 512);
            attn_kernel<<<dim3(4, 32), 128>>>();
            gemm_kernel<2><<<dim3(8, 8, 1), 256>>>(pat, wo, wo, wo, ptmp, ptmp, ptmp,
                                                   nullptr, ph, 512, 512);
            ln_kernel<<<512, 128>>>(ptmp, ln1g + l * 512, ln1b + l * 512, ph);
            gemm_kernel<1><<<dim3(32, 8, 1), 256>>>(ph, w1, w1, w1, pff, pff, pff,
                                                    b1 + l * D_FF, nullptr, 2048, 512);
            gemm_kernel<3><<<dim3(8, 8, 1), 256>>>(pff, w2, w2, w2, ptmp, ptmp, ptmp,
                                                   b2 + l * 512, ph, 512, 2048);
            ln_kernel<<<512, 128>>>(ptmp, ln2g + l * 512, ln2b + l * 512, ph);
        }
        for (int s = 0; s < N_SUB; s++) {
            refineA_kernel<<<64, 256>>>(Wemb, bemb, Wr1, br1, step, s == 0);
            refineB_kernel<<<4, 256>>>(Wr2, br2, out, step, s == 0, s == N_SUB - 1);
        }
    }
}

// round 4
// speedup vs baseline: 1.0207x; 1.0207x over previous
#include <cuda_runtime.h>
#include <math.h>

typedef unsigned long long u64;
#define DEV __device__ __forceinline__

constexpr int B = 4, TH = 120, STEPS = 8, D_IN = 32, D_MODEL = 512;
constexpr int N_HEADS = 8, N_LAYERS = 4, D_FF = 2048, N_SUB = 5;
constexpr int T = 128;          // TH + STEPS
constexpr int M = 512;          // B * T
constexpr float LN_EPS = 1e-5f;
constexpr float NEGMIN = -3.402823466e38f;
constexpr float EMB_SCALE = 22.627416997969522f;   // sqrt(512)
constexpr float INV_SQRT_DH = 0.125f;              // 1/sqrt(64)

// -------- device scratch (no allocations allowed) --------
__device__ float g_buf[B][T][D_IN];
__device__ float g_h[M][D_MODEL];
__device__ float g_q[M][D_MODEL];
__device__ float g_k[M][D_MODEL];
__device__ float g_v[M][D_MODEL];
__device__ float g_attn[M][D_MODEL];
__device__ float g_tmp[M][D_MODEL];
__device__ float g_ff[M][D_FF];
__device__ float g_cur[B][D_IN];
__device__ float g_ffr[B][D_FF];

// -------- packed f32x2 helpers (bitwise == scalar FFMA) --------
DEV u64 pack2(float lo, float hi) {
    u64 r; asm("mov.b64 %0, {%1, %2};" : "=l"(r) : "f"(lo), "f"(hi)); return r;
}
DEV float2 unpack2(u64 v) {
    float2 r; asm("mov.b64 {%0, %1}, %2;" : "=f"(r.x), "=f"(r.y) : "l"(v)); return r;
}
DEV void fma2(u64& c, u64 a, u64 b) {
    asm("fma.rn.f32x2 %0, %1, %2, %0;" : "+l"(c) : "l"(a), "l"(b));
}
union F4U { float4 f; u64 u[2]; };

DEV float gelu(float x) {
    return 0.5f * x * (1.0f + tanhf(0.7978845608028654f * (x + 0.044715f * x * x * x)));
}

// =============== buf init (every replay; deterministic) ===============
__global__ void init_buf_kernel(const float* __restrict__ history) {
    int b = blockIdx.x;
    for (int idx = threadIdx.x; idx < T * D_IN; idx += blockDim.x) {
        int t = idx >> 5, i = idx & 31;
        g_buf[b][t][i] = (t < TH) ? history[(b * TH + t) * D_IN + i] : 0.0f;
    }
}

// =============== embedding + positional encoding ===============
__global__ void embed_kernel(const float* __restrict__ Wemb,
                             const float* __restrict__ bemb) {
    int row = blockIdx.x;              // b*T + t
    int t = row & (T - 1);
    int b = row >> 7;
    __shared__ float xs[D_IN];
    int tid = threadIdx.x;             // 128
    if (tid < D_IN) xs[tid] = g_buf[b][t][tid];
    __syncthreads();
#pragma unroll
    for (int c = 0; c < 4; c++) {
        int d = tid + c * 128;
        const float* w = Wemb + d * D_IN;
        float s = 0.0f;
#pragma unroll
        for (int i = 0; i < D_IN; i += 4) {
            float4 wv = *(const float4*)&w[i];
            s += wv.x * xs[i] + wv.y * xs[i + 1] + wv.z * xs[i + 2] + wv.w * xs[i + 3];
        }
        s = (s + bemb[d]) * EMB_SCALE;
        int j2 = d & ~1;
        float ang = (float)t * expf((float)j2 * (-9.210340371976184f / 512.0f));
        s += (d & 1) ? cosf(ang) : sinf(ang);
        g_h[row][d] = s;
    }
}

// =============== GEMM: C[M,N] = A[M,K] @ W[N,K]^T (+ epilogue) ===============
// EPI: 0 none | 1 gelu(c+bias) | 2 c+res | 3 c+bias+res
template <int BM, int BN, int EPI>
__global__ void __launch_bounds__(256) gemm_kernel(
    const float* __restrict__ A,
    const float* __restrict__ W0, const float* __restrict__ W1p,
    const float* __restrict__ W2p,
    float* __restrict__ O0, float* __restrict__ O1, float* __restrict__ O2,
    const float* __restrict__ bias, const float* __restrict__ res,
    int N, int K) {
    constexpr int TM = BM / 16;          // rows per thread (4 or 8)
    constexpr int TN = BN / 16;          // cols per thread (2 or 4)
    constexpr int NA = (BM * 4) / 256;   // A float4 loads per thread (1 or 2)
    constexpr bool WFULL = (BN * 4 >= 256);

    const float* __restrict__ W = blockIdx.z == 0 ? W0 : (blockIdx.z == 1 ? W1p : W2p);
    float* __restrict__ O = blockIdx.z == 0 ? O0 : (blockIdx.z == 1 ? O1 : O2);

    __shared__ __align__(16) float As[16][BM + 4];
    __shared__ __align__(16) float Ws[16][BN + 4];

    int tid = threadIdx.x;
    int tx = tid & 15, ty = tid >> 4;
    int m0 = blockIdx.y * BM, n0 = blockIdx.x * BN;

    u64 acc[TM][TN / 2];
#pragma unroll
    for (int i = 0; i < TM; i++)
#pragma unroll
        for (int j = 0; j < TN / 2; j++) acc[i][j] = pack2(0.0f, 0.0f);

    F4U av[NA], wv;
#pragma unroll
    for (int i = 0; i < NA; i++) {
        int idx = tid + i * 256;
        av[i].f = *(const float4*)&A[(m0 + (idx >> 2)) * K + (idx & 3) * 4];
    }
    bool wp = WFULL || (tid < BN * 4);
    if (wp) wv.f = *(const float4*)&W[(n0 + (tid >> 2)) * K + (tid & 3) * 4];

    for (int kt = 0; kt < K; kt += 16) {
#pragma unroll
        for (int i = 0; i < NA; i++) {
            int idx = tid + i * 256;
            int r = idx >> 2, kq = idx & 3;
            As[kq * 4 + 0][r] = av[i].f.x; As[kq * 4 + 1][r] = av[i].f.y;
            As[kq * 4 + 2][r] = av[i].f.z; As[kq * 4 + 3][r] = av[i].f.w;
        }
        if (wp) {
            int r = tid >> 2, kq = tid & 3;
            Ws[kq * 4 + 0][r] = wv.f.x; Ws[kq * 4 + 1][r] = wv.f.y;
            Ws[kq * 4 + 2][r] = wv.f.z; Ws[kq * 4 + 3][r] = wv.f.w;
        }
        __syncthreads();
        if (kt + 16 < K) {
#pragma unroll
            for (int i = 0; i < NA; i++) {
                int idx = tid + i * 256;
                av[i].f = *(const float4*)&A[(m0 + (idx >> 2)) * K + kt + 16 + (idx & 3) * 4];
            }
            if (wp) wv.f = *(const float4*)&W[(n0 + (tid >> 2)) * K + kt + 16 + (tid & 3) * 4];
        }
#pragma unroll
        for (int kk = 0; kk < 16; kk++) {
            u64 w2[TN / 2];
            if (TN == 2) {
                w2[0] = *(const u64*)&Ws[kk][tx * 2];
            } else {
                F4U wr; wr.f = *(const float4*)&Ws[kk][tx * 4];
                w2[0] = wr.u[0]; w2[1] = wr.u[1];
            }
            float a[TM];
#pragma unroll
            for (int g = 0; g < TM / 4; g++) {
                F4U ar; ar.f = *(const float4*)&As[kk][ty * TM + g * 4];
                a[g * 4 + 0] = ar.f.x; a[g * 4 + 1] = ar.f.y;
                a[g * 4 + 2] = ar.f.z; a[g * 4 + 3] = ar.f.w;
            }
#pragma unroll
            for (int i = 0; i < TM; i++) {
                u64 a2 = pack2(a[i], a[i]);
#pragma unroll
                for (int j = 0; j < TN / 2; j++) fma2(acc[i][j], a2, w2[j]);
            }
        }
        __syncthreads();
    }

    int col = n0 + tx * TN;
#pragma unroll
    for (int i = 0; i < TM; i++) {
        int row = m0 + ty * TM + i;
        float c[TN];
#pragma unroll
        for (int j = 0; j < TN / 2; j++) {
            float2 p = unpack2(acc[i][j]);
            c[j * 2] = p.x; c[j * 2 + 1] = p.y;
        }
        if (EPI == 1) {
#pragma unroll
            for (int j = 0; j < TN; j++) c[j] = gelu(c[j] + bias[col + j]);
        } else if (EPI == 2) {
#pragma unroll
            for (int j = 0; j < TN; j++) c[j] += res[row * N + col + j];
        } else if (EPI == 3) {
#pragma unroll
            for (int j = 0; j < TN; j++) c[j] += res[row * N + col + j] + bias[col + j];
        }
        if (TN == 4) {
            float4 o4 = {c[0], c[1], c[2], c[3]};
            *(float4*)&O[row * N + col] = o4;
        } else {
            float2 o2 = {c[0], c[1]};
            *(float2*)&O[row * N + col] = o2;
        }
    }
}

// =============== LayerNorm (row-wise, D=512) ===============
__global__ void ln_kernel(const float* __restrict__ X,
                          const float* __restrict__ gam,
                          const float* __restrict__ bet,
                          float* __restrict__ O) {
    int row = blockIdx.x;
    int tid = threadIdx.x;   // 128
    __shared__ float red[4];
    float4 x = *(const float4*)&X[row * 512 + tid * 4];
    float s = x.x + x.y + x.z + x.w;
#pragma unroll
    for (int o = 16; o; o >>= 1) s += __shfl_xor_sync(~0u, s, o);
    if ((tid & 31) == 0) red[tid >> 5] = s;
    __syncthreads();
    float mu = (red[0] + red[1] + red[2] + red[3]) * (1.0f / 512.0f);
    float dx = x.x - mu, dy = x.y - mu, dz = x.z - mu, dw = x.w - mu;
    float v = dx * dx + dy * dy + dz * dz + dw * dw;
#pragma unroll
    for (int o = 16; o; o >>= 1) v += __shfl_xor_sync(~0u, v, o);
    __syncthreads();
    if ((tid & 31) == 0) red[tid >> 5] = v;
    __syncthreads();
    float var = (red[0] + red[1] + red[2] + red[3]) * (1.0f / 512.0f);
    float inv = 1.0f / sqrtf(var + LN_EPS);
    int c = tid * 4;
    float4 o4;
    o4.x = dx * inv * gam[c + 0] + bet[c + 0];
    o4.y = dy * inv * gam[c + 1] + bet[c + 1];
    o4.z = dz * inv * gam[c + 2] + bet[c + 2];
    o4.w = dw * inv * gam[c + 3] + bet[c + 3];
    *(float4*)&O[row * 512 + c] = o4;
}

// =============== Attention v2: thread = (q-row, k-group of 32) ===============
// mask: attend where key index > query index (anti-causal, faithful to source)
__global__ void __launch_bounds__(128) attn_kernel() {
    __shared__ __align__(16) float Ks[128][68];
    int qt = blockIdx.x, bh = blockIdx.y;
    int b = bh >> 3, h = bh & 7;
    int tid = threadIdx.x;
    int qr = tid >> 2, kg = tid & 3;
    int qi = qt * 32 + qr;
    int base = b * T;
    int hc = h * 64;

    // stage K tile [128 x 64] in smem
    for (int i = tid; i < 128 * 16; i += 128) {
        int r = i >> 4, c = i & 15;
        *(float4*)&Ks[r][c * 4] = *(const float4*)&g_k[base + r][hc + c * 4];
    }
    // q row in registers
    F4U q[16];
#pragma unroll
    for (int c = 0; c < 16; c++)
        q[c].f = *(const float4*)&g_q[base + qi][hc + c * 4];
    __syncthreads();

    // logits for own 32 keys (k = kg*32 + j), 4 independent accumulators
    float prob[32];
    float mloc = NEGMIN;
#pragma unroll
    for (int j = 0; j < 32; j++) {
        int k = kg * 32 + j;
        u64 a0 = pack2(0.f, 0.f), a1 = a0, a2 = a0, a3 = a0;
#pragma unroll
        for (int c = 0; c < 16; c += 2) {
            F4U k0; k0.f = *(const float4*)&Ks[k][c * 4];
            F4U k1; k1.f = *(const float4*)&Ks[k][c * 4 + 4];
            fma2(a0, q[c].u[0], k0.u[0]);
            fma2(a1, q[c].u[1], k0.u[1]);
            fma2(a2, q[c + 1].u[0], k1.u[0]);
            fma2(a3, q[c + 1].u[1], k1.u[1]);
        }
        float2 p0 = unpack2(a0), p1 = unpack2(a1), p2 = unpack2(a2), p3 = unpack2(a3);
        float s = (p0.x + p0.y) + (p1.x + p1.y) + (p2.x + p2.y) + (p3.x + p3.y);
        s = (k > qi) ? s * INV_SQRT_DH : NEGMIN;
        prob[j] = s;
        mloc = fmaxf(mloc, s);
    }
    // reduce max over the 4 kg-threads of this q-row
    mloc = fmaxf(mloc, __shfl_xor_sync(~0u, mloc, 1));
    mloc = fmaxf(mloc, __shfl_xor_sync(~0u, mloc, 2));
    float lsum = 0.0f;
#pragma unroll
    for (int j = 0; j < 32; j++) {
        float p = expf(prob[j] - mloc);
        prob[j] = p;
        lsum += p;
    }
    lsum += __shfl_xor_sync(~0u, lsum, 1);
    lsum += __shfl_xor_sync(~0u, lsum, 2);

    __syncthreads();   // done reading K
    // stage V tile
    for (int i = tid; i < 128 * 16; i += 128) {
        int r = i >> 4, c = i & 15;
        *(float4*)&Ks[r][c * 4] = *(const float4*)&g_v[base + r][hc + c * 4];
    }
    __syncthreads();

    // partial o over own 32 keys, all 64 dims
    F4U o[16];
#pragma unroll
    for (int c = 0; c < 16; c++) { o[c].u[0] = pack2(0.f, 0.f); o[c].u[1] = pack2(0.f, 0.f); }
#pragma unroll 4
    for (int j = 0; j < 32; j++) {
        int k = kg * 32 + j;
        u64 pw = pack2(prob[j], prob[j]);
#pragma unroll
        for (int c = 0; c < 16; c++) {
            F4U vv; vv.f = *(const float4*)&Ks[k][c * 4];
            fma2(o[c].u[0], pw, vv.u[0]);
            fma2(o[c].u[1], pw, vv.u[1]);
        }
    }
    __syncthreads();   // done reading V
    // cross-thread reduce via smem: row (kg*32 + qr) holds this thread's partial
    float* po = &Ks[kg * 32 + qr][0];
#pragma unroll
    for (int c = 0; c < 16; c++) *(float4*)&po[c * 4] = o[c].f;
    __syncthreads();

    float invl = 1.0f / lsum;
#pragma unroll
    for (int c = 0; c < 4; c++) {
        int d = kg * 16 + c * 4;
        float4 s0 = *(const float4*)&Ks[qr][d];
        float4 s1 = *(const float4*)&Ks[32 + qr][d];
        float4 s2 = *(const float4*)&Ks[64 + qr][d];
        float4 s3 = *(const float4*)&Ks[96 + qr][d];
        float4 r4;
        r4.x = (s0.x + s1.x + s2.x + s3.x) * invl;
        r4.y = (s0.y + s1.y + s2.y + s3.y) * invl;
        r4.z = (s0.z + s1.z + s2.z + s3.z) * invl;
        r4.w = (s0.w + s1.w + s2.w + s3.w) * invl;
        *(float4*)&g_attn[base + qi][hc + d] = r4;
    }
}

// =============== refine head, stage A: comb -> ff (2048 rows) ===============
__global__ void __launch_bounds__(256) refineA_kernel(
    const float* __restrict__ Wemb, const float* __restrict__ bemb,
    const float* __restrict__ Wr1, const float* __restrict__ br1,
    int step, int first) {
    int b = blockIdx.x >> 4, part = blockIdx.x & 15;
    __shared__ float comb[1024];
    __shared__ float cur[32];
    int tid = threadIdx.x;
    int ptr = TH + step;
    if (tid < 32) cur[tid] = first ? g_buf[b][ptr - 1][tid] : g_cur[b][tid];
    __syncthreads();
    for (int d = tid; d < 512; d += 256) {
        const float* w = &Wemb[d * 32];
        float s = 0.0f;
#pragma unroll
        for (int i = 0; i < 32; i += 4) {
            float4 wv = *(const float4*)&w[i];
            s += wv.x * cur[i] + wv.y * cur[i + 1] + wv.z * cur[i + 2] + wv.w * cur[i + 3];
        }
        comb[d] = (s + bemb[d]) * EMB_SCALE;
    }
    for (int d = tid; d < 512; d += 256) comb[512 + d] = g_h[b * T + ptr - 1][d];
    __syncthreads();

    int r = part * 128 + (tid >> 1);
    int half = tid & 1;
    const float* w = &Wr1[r * 1024 + half * 512];
    const float* cb = &comb[half * 512];
    u64 a0 = pack2(0.f, 0.f), a1 = pack2(0.f, 0.f);
    for (int i = 0; i < 512; i += 4) {
        F4U wv; wv.f = *(const float4*)&w[i];
        F4U cv; cv.f = *(const float4*)&cb[i];
        fma2(a0, wv.u[0], cv.u[0]);
        fma2(a1, wv.u[1], cv.u[1]);
    }
    float2 x0 = unpack2(a0), x1 = unpack2(a1);
    float s = x0.x + x0.y + x1.x + x1.y;
    s += __shfl_xor_sync(~0u, s, 1);
    if (half == 0) g_ffr[b][r] = gelu(s + br1[r]);
}

// =============== refine head, stage B: delta + cur update ===============
__global__ void __launch_bounds__(256) refineB_kernel(
    const float* __restrict__ Wr2, const float* __restrict__ br2,
    float* __restrict__ out, int step, int first, int last) {
    int b = blockIdx.x;
    int tid = threadIdx.x;
    __shared__ float ff[2048];
    for (int i = tid; i < 2048; i += 256) ff[i] = g_ffr[b][i];
    __syncthreads();
    int i = tid >> 3, part = tid & 7;
    const float* w = &Wr2[i * 2048 + part * 256];
    const float* f = &ff[part * 256];
    u64 a0 = pack2(0.f, 0.f), a1 = pack2(0.f, 0.f);
    for (int j = 0; j < 256; j += 4) {
        F4U wv; wv.f = *(const float4*)&w[j];
        F4U fv; fv.f = *(const float4*)&f[j];
        fma2(a0, wv.u[0], fv.u[0]);
        fma2(a1, wv.u[1], fv.u[1]);
    }
    float2 x0 = unpack2(a0), x1 = unpack2(a1);
    float s = x0.x + x0.y + x1.x + x1.y;
    s += __shfl_xor_sync(~0u, s, 1);
    s += __shfl_xor_sync(~0u, s, 2);
    s += __shfl_xor_sync(~0u, s, 4);
    if (part == 0) {
        int ptr = TH + step;
        float base = first ? g_buf[b][ptr - 1][i] : g_cur[b][i];
        float nv = base + s + br2[i];
        g_cur[b][i] = nv;
        if (last) {
            g_buf[b][ptr][i] = nv;
            out[(b * STEPS + step) * D_IN + i] = nv;
        }
    }
}

// =============== host orchestration ===============
extern "C" void kernel_launch(void* const* d_in, const int* in_sizes, int n_in,
                              void* d_out, int out_size) {
    int o = (n_in >= 20) ? 1 : 0;   // "steps" scalar occupies index 1 if present
    const float* history = (const float*)d_in[0];
    const float* Wemb = (const float*)d_in[1 + o];
    const float* bemb = (const float*)d_in[2 + o];
    const float* Wq = (const float*)d_in[3 + o];
    const float* Wk = (const float*)d_in[4 + o];
    const float* Wv = (const float*)d_in[5 + o];
    const float* Wo = (const float*)d_in[6 + o];
    const float* ln1g = (const float*)d_in[7 + o];
    const float* ln1b = (const float*)d_in[8 + o];
    const float* W1 = (const float*)d_in[9 + o];
    const float* b1 = (const float*)d_in[10 + o];
    const float* W2 = (const float*)d_in[11 + o];
    const float* b2 = (const float*)d_in[12 + o];
    const float* ln2g = (const float*)d_in[13 + o];
    const float* ln2b = (const float*)d_in[14 + o];
    const float* Wr1 = (const float*)d_in[15 + o];
    const float* br1 = (const float*)d_in[16 + o];
    const float* Wr2 = (const float*)d_in[17 + o];
    const float* br2 = (const float*)d_in[18 + o];
    float* out = (float*)d_out;

    void* p;
    cudaGetSymbolAddress(&p, g_h);    float* ph = (float*)p;
    cudaGetSymbolAddress(&p, g_q);    float* pq = (float*)p;
    cudaGetSymbolAddress(&p, g_k);    float* pk = (float*)p;
    cudaGetSymbolAddress(&p, g_v);    float* pv = (float*)p;
    cudaGetSymbolAddress(&p, g_attn); float* pat = (float*)p;
    cudaGetSymbolAddress(&p, g_tmp);  float* ptmp = (float*)p;
    cudaGetSymbolAddress(&p, g_ff);   float* pff = (float*)p;

    init_buf_kernel<<<B, 256>>>(history);

    for (int step = 0; step < STEPS; step++) {
        embed_kernel<<<M, 128>>>(Wemb, bemb);
        for (int l = 0; l < N_LAYERS; l++) {
            const float* wq = Wq + l * D_MODEL * D_MODEL;
            const float* wk = Wk + l * D_MODEL * D_MODEL;
            const float* wv = Wv + l * D_MODEL * D_MODEL;
            const float* wo = Wo + l * D_MODEL * D_MODEL;
            const float* w1 = W1 + l * D_FF * D_MODEL;
            const float* w2 = W2 + l * D_MODEL * D_FF;

            gemm_kernel<64, 32, 0><<<dim3(16, 8, 3), 256>>>(
                ph, wq, wk, wv, pq, pk, pv, nullptr, nullptr, 512, 512);
            attn_kernel<<<dim3(4, 32), 128>>>();
            gemm_kernel<64, 32, 2><<<dim3(16, 8, 1), 256>>>(
                pat, wo, wo, wo, ptmp, ptmp, ptmp, nullptr, ph, 512, 512);
            ln_kernel<<<512, 128>>>(ptmp, ln1g + l * 512, ln1b + l * 512, ph);
            gemm_kernel<128, 64, 1><<<dim3(32, 4, 1), 256>>>(
                ph, w1, w1, w1, pff, pff, pff, b1 + l * D_FF, nullptr, 2048, 512);
            gemm_kernel<64, 32, 3><<<dim3(16, 8, 1), 256>>>(
                pff, w2, w2, w2, ptmp, ptmp, ptmp, b2 + l * 512, ph, 512, 2048);
            ln_kernel<<<512, 128>>>(ptmp, ln2g + l * 512, ln2b + l * 512, ph);
        }
        for (int s = 0; s < N_SUB; s++) {
            refineA_kernel<<<64, 256>>>(Wemb, bemb, Wr1, br1, step, s == 0);
            refineB_kernel<<<4, 256>>>(Wr2, br2, out, step, s == 0, s == N_SUB - 1);
        }
    }
}

// round 6
// speedup vs baseline: 1.1075x; 1.0849x over previous
#include <cuda_runtime.h>
#include <math.h>

typedef unsigned long long u64;
#define DEV __device__ __forceinline__

constexpr int B = 4, TH = 120, STEPS = 8, D_IN = 32, D_MODEL = 512;
constexpr int N_HEADS = 8, N_LAYERS = 4, D_FF = 2048, N_SUB = 5;
constexpr int T = 128;          // TH + STEPS
constexpr int M = 512;          // B * T
constexpr float LN_EPS = 1e-5f;
constexpr float NEGMIN = -3.402823466e38f;
constexpr float EMB_SCALE = 22.627416997969522f;   // sqrt(512)
constexpr float INV_SQRT_DH = 0.125f;              // 1/sqrt(64)

// -------- device scratch (no allocations allowed) --------
__device__ float g_buf[B][T][D_IN];
__device__ float g_h[M][D_MODEL];
__device__ float g_q[M][D_MODEL];
__device__ float g_k[M][D_MODEL];
__device__ float g_v[M][D_MODEL];
__device__ float g_attn[M][D_MODEL];
__device__ float g_tmp[M][D_MODEL];
__device__ float g_ff[M][D_FF];
__device__ float g_cur[B][D_IN];
__device__ float g_ffr[B][D_FF];

// -------- packed f32x2 helpers (bitwise == scalar FFMA) --------
DEV u64 pack2(float lo, float hi) {
    u64 r; asm("mov.b64 %0, {%1, %2};" : "=l"(r) : "f"(lo), "f"(hi)); return r;
}
DEV float2 unpack2(u64 v) {
    float2 r; asm("mov.b64 {%0, %1}, %2;" : "=f"(r.x), "=f"(r.y) : "l"(v)); return r;
}
DEV void fma2(u64& c, u64 a, u64 b) {
    asm("fma.rn.f32x2 %0, %1, %2, %0;" : "+l"(c) : "l"(a), "l"(b));
}
union F4U { float4 f; u64 u[2]; };

DEV float gelu(float x) {
    return 0.5f * x * (1.0f + tanhf(0.7978845608028654f * (x + 0.044715f * x * x * x)));
}

// =============== buf init (every replay; deterministic) ===============
__global__ void init_buf_kernel(const float* __restrict__ history) {
    int b = blockIdx.x;
    for (int idx = threadIdx.x; idx < T * D_IN; idx += blockDim.x) {
        int t = idx >> 5, i = idx & 31;
        g_buf[b][t][i] = (t < TH) ? history[(b * TH + t) * D_IN + i] : 0.0f;
    }
}

// =============== embedding + positional encoding ===============
__global__ void embed_kernel(const float* __restrict__ Wemb,
                             const float* __restrict__ bemb) {
    int row = blockIdx.x;              // b*T + t
    int t = row & (T - 1);
    int b = row >> 7;
    __shared__ float xs[D_IN];
    int tid = threadIdx.x;             // 128
    if (tid < D_IN) xs[tid] = g_buf[b][t][tid];
    __syncthreads();
#pragma unroll
    for (int c = 0; c < 4; c++) {
        int d = tid + c * 128;
        const float* w = Wemb + d * D_IN;
        float s = 0.0f;
#pragma unroll
        for (int i = 0; i < D_IN; i += 4) {
            float4 wv = *(const float4*)&w[i];
            s += wv.x * xs[i] + wv.y * xs[i + 1] + wv.z * xs[i + 2] + wv.w * xs[i + 3];
        }
        s = (s + bemb[d]) * EMB_SCALE;
        int j2 = d & ~1;
        float ang = (float)t * expf((float)j2 * (-9.210340371976184f / 512.0f));
        s += (d & 1) ? cosf(ang) : sinf(ang);
        g_h[row][d] = s;
    }
}

// =============== GEMM: C[M,N] = A[M,K] @ W[N,K]^T (+ epilogue) ===============
// EPI: 0 none | 1 gelu(c+bias) | 2 c+res | 3 c+bias+res
template <int BM, int BN, int EPI>
__global__ void __launch_bounds__(256) gemm_kernel(
    const float* __restrict__ A,
    const float* __restrict__ W0, const float* __restrict__ W1p,
    const float* __restrict__ W2p,
    float* __restrict__ O0, float* __restrict__ O1, float* __restrict__ O2,
    const float* __restrict__ bias, const float* __restrict__ res,
    int N, int K) {
    constexpr int TM = BM / 16;          // rows per thread
    constexpr int TN = BN / 16;          // cols per thread
    constexpr int NA = (BM * 4) / 256;   // A float4 loads per thread
    constexpr bool WFULL = (BN * 4 >= 256);

    const float* __restrict__ W = blockIdx.z == 0 ? W0 : (blockIdx.z == 1 ? W1p : W2p);
    float* __restrict__ O = blockIdx.z == 0 ? O0 : (blockIdx.z == 1 ? O1 : O2);

    __shared__ __align__(16) float As[16][BM + 4];
    __shared__ __align__(16) float Ws[16][BN + 4];

    int tid = threadIdx.x;
    int tx = tid & 15, ty = tid >> 4;
    int m0 = blockIdx.y * BM, n0 = blockIdx.x * BN;

    u64 acc[TM][TN / 2];
#pragma unroll
    for (int i = 0; i < TM; i++)
#pragma unroll
        for (int j = 0; j < TN / 2; j++) acc[i][j] = pack2(0.0f, 0.0f);

    F4U av[NA], wv;
#pragma unroll
    for (int i = 0; i < NA; i++) {
        int idx = tid + i * 256;
        av[i].f = *(const float4*)&A[(m0 + (idx >> 2)) * K + (idx & 3) * 4];
    }
    bool wp = WFULL || (tid < BN * 4);
    if (wp) wv.f = *(const float4*)&W[(n0 + (tid >> 2)) * K + (tid & 3) * 4];

    for (int kt = 0; kt < K; kt += 16) {
#pragma unroll
        for (int i = 0; i < NA; i++) {
            int idx = tid + i * 256;
            int r = idx >> 2, kq = idx & 3;
            As[kq * 4 + 0][r] = av[i].f.x; As[kq * 4 + 1][r] = av[i].f.y;
            As[kq * 4 + 2][r] = av[i].f.z; As[kq * 4 + 3][r] = av[i].f.w;
        }
        if (wp) {
            int r = tid >> 2, kq = tid & 3;
            Ws[kq * 4 + 0][r] = wv.f.x; Ws[kq * 4 + 1][r] = wv.f.y;
            Ws[kq * 4 + 2][r] = wv.f.z; Ws[kq * 4 + 3][r] = wv.f.w;
        }
        __syncthreads();
        if (kt + 16 < K) {
#pragma unroll
            for (int i = 0; i < NA; i++) {
                int idx = tid + i * 256;
                av[i].f = *(const float4*)&A[(m0 + (idx >> 2)) * K + kt + 16 + (idx & 3) * 4];
            }
            if (wp) wv.f = *(const float4*)&W[(n0 + (tid >> 2)) * K + kt + 16 + (tid & 3) * 4];
        }
#pragma unroll
        for (int kk = 0; kk < 16; kk++) {
            u64 w2[TN / 2];
            if (TN == 2) {
                w2[0] = *(const u64*)&Ws[kk][tx * 2];
            } else {
                F4U wr; wr.f = *(const float4*)&Ws[kk][tx * 4];
                w2[0] = wr.u[0]; w2[1] = wr.u[1];
            }
            float a[TM];
#pragma unroll
            for (int g = 0; g < TM / 4; g++) {
                F4U ar; ar.f = *(const float4*)&As[kk][ty * TM + g * 4];
                a[g * 4 + 0] = ar.f.x; a[g * 4 + 1] = ar.f.y;
                a[g * 4 + 2] = ar.f.z; a[g * 4 + 3] = ar.f.w;
            }
#pragma unroll
            for (int i = 0; i < TM; i++) {
                u64 a2 = pack2(a[i], a[i]);
#pragma unroll
                for (int j = 0; j < TN / 2; j++) fma2(acc[i][j], a2, w2[j]);
            }
        }
        __syncthreads();
    }

    int col = n0 + tx * TN;
#pragma unroll
    for (int i = 0; i < TM; i++) {
        int row = m0 + ty * TM + i;
        float c[TN];
#pragma unroll
        for (int j = 0; j < TN / 2; j++) {
            float2 p = unpack2(acc[i][j]);
            c[j * 2] = p.x; c[j * 2 + 1] = p.y;
        }
        if (EPI == 1) {
#pragma unroll
            for (int j = 0; j < TN; j++) c[j] = gelu(c[j] + bias[col + j]);
        } else if (EPI == 2) {
#pragma unroll
            for (int j = 0; j < TN; j++) c[j] += res[row * N + col + j];
        } else if (EPI == 3) {
#pragma unroll
            for (int j = 0; j < TN; j++) c[j] += res[row * N + col + j] + bias[col + j];
        }
        if (TN == 4) {
            float4 o4 = {c[0], c[1], c[2], c[3]};
            *(float4*)&O[row * N + col] = o4;
        } else {
            float2 o2 = {c[0], c[1]};
            *(float2*)&O[row * N + col] = o2;
        }
    }
}

// =============== LayerNorm (row-wise, D=512) ===============
__global__ void ln_kernel(const float* __restrict__ X,
                          const float* __restrict__ gam,
                          const float* __restrict__ bet,
                          float* __restrict__ O) {
    int row = blockIdx.x;
    int tid = threadIdx.x;   // 128
    __shared__ float red[4];
    float4 x = *(const float4*)&X[row * 512 + tid * 4];
    float s = x.x + x.y + x.z + x.w;
#pragma unroll
    for (int o = 16; o; o >>= 1) s += __shfl_xor_sync(~0u, s, o);
    if ((tid & 31) == 0) red[tid >> 5] = s;
    __syncthreads();
    float mu = (red[0] + red[1] + red[2] + red[3]) * (1.0f / 512.0f);
    float dx = x.x - mu, dy = x.y - mu, dz = x.z - mu, dw = x.w - mu;
    float v = dx * dx + dy * dy + dz * dz + dw * dw;
#pragma unroll
    for (int o = 16; o; o >>= 1) v += __shfl_xor_sync(~0u, v, o);
    __syncthreads();
    if ((tid & 31) == 0) red[tid >> 5] = v;
    __syncthreads();
    float var = (red[0] + red[1] + red[2] + red[3]) * (1.0f / 512.0f);
    float inv = 1.0f / sqrtf(var + LN_EPS);
    int c = tid * 4;
    float4 o4;
    o4.x = dx * inv * gam[c + 0] + bet[c + 0];
    o4.y = dy * inv * gam[c + 1] + bet[c + 1];
    o4.z = dz * inv * gam[c + 2] + bet[c + 2];
    o4.w = dw * inv * gam[c + 3] + bet[c + 3];
    *(float4*)&O[row * 512 + c] = o4;
}

// =============== Attention v3: thread = (q-row, k-group), INTERLEAVED keys ===
// Thread kg owns keys k = kg + 4*j  (j = 0..31). At each j the four kg threads
// read K rows 4j..4j+3 whose smem banks differ by 4 (68*kg mod 32) -> the four
// float4 reads cover disjoint bank groups -> conflict-free (v2 had rows 32
// apart = identical banks = 4-way conflict on every LDS).
// mask: attend where key index > query index (anti-causal, faithful to source)
__global__ void __launch_bounds__(128) attn_kernel() {
    __shared__ __align__(16) float Ks[128][68];
    int qt = blockIdx.x, bh = blockIdx.y;
    int b = bh >> 3, h = bh & 7;
    int tid = threadIdx.x;
    int qr = tid >> 2, kg = tid & 3;
    int qi = qt * 32 + qr;
    int base = b * T;
    int hc = h * 64;

    // stage K tile [128 x 64] in smem
    for (int i = tid; i < 128 * 16; i += 128) {
        int r = i >> 4, c = i & 15;
        *(float4*)&Ks[r][c * 4] = *(const float4*)&g_k[base + r][hc + c * 4];
    }
    // q row in registers
    F4U q[16];
#pragma unroll
    for (int c = 0; c < 16; c++)
        q[c].f = *(const float4*)&g_q[base + qi][hc + c * 4];
    __syncthreads();

    // logits for own 32 keys (k = kg + 4*j), 4 independent accumulators
    float prob[32];
    float mloc = NEGMIN;
#pragma unroll
    for (int j = 0; j < 32; j++) {
        int k = kg + 4 * j;
        u64 a0 = pack2(0.f, 0.f), a1 = a0, a2 = a0, a3 = a0;
#pragma unroll
        for (int c = 0; c < 16; c += 2) {
            F4U k0; k0.f = *(const float4*)&Ks[k][c * 4];
            F4U k1; k1.f = *(const float4*)&Ks[k][c * 4 + 4];
            fma2(a0, q[c].u[0], k0.u[0]);
            fma2(a1, q[c].u[1], k0.u[1]);
            fma2(a2, q[c + 1].u[0], k1.u[0]);
            fma2(a3, q[c + 1].u[1], k1.u[1]);
        }
        float2 p0 = unpack2(a0), p1 = unpack2(a1), p2 = unpack2(a2), p3 = unpack2(a3);
        float s = (p0.x + p0.y) + (p1.x + p1.y) + (p2.x + p2.y) + (p3.x + p3.y);
        s = (k > qi) ? s * INV_SQRT_DH : NEGMIN;
        prob[j] = s;
        mloc = fmaxf(mloc, s);
    }
    // reduce max over the 4 kg-threads of this q-row (lanes differ in bits 0..1)
    mloc = fmaxf(mloc, __shfl_xor_sync(~0u, mloc, 1));
    mloc = fmaxf(mloc, __shfl_xor_sync(~0u, mloc, 2));
    float lsum = 0.0f;
#pragma unroll
    for (int j = 0; j < 32; j++) {
        float p = expf(prob[j] - mloc);
        prob[j] = p;
        lsum += p;
    }
    lsum += __shfl_xor_sync(~0u, lsum, 1);
    lsum += __shfl_xor_sync(~0u, lsum, 2);

    __syncthreads();   // done reading K
    // stage V tile
    for (int i = tid; i < 128 * 16; i += 128) {
        int r = i >> 4, c = i & 15;
        *(float4*)&Ks[r][c * 4] = *(const float4*)&g_v[base + r][hc + c * 4];
    }
    __syncthreads();

    // partial o over own 32 keys (same interleaving), all 64 dims
    F4U o[16];
#pragma unroll
    for (int c = 0; c < 16; c++) { o[c].u[0] = pack2(0.f, 0.f); o[c].u[1] = pack2(0.f, 0.f); }
#pragma unroll 4
    for (int j = 0; j < 32; j++) {
        int k = kg + 4 * j;
        u64 pw = pack2(prob[j], prob[j]);
#pragma unroll
        for (int c = 0; c < 16; c++) {
            F4U vv; vv.f = *(const float4*)&Ks[k][c * 4];
            fma2(o[c].u[0], pw, vv.u[0]);
            fma2(o[c].u[1], pw, vv.u[1]);
        }
    }
    __syncthreads();   // done reading V
    // cross-thread reduce via smem: row (kg*32 + qr) holds this thread's partial
    float* po = &Ks[kg * 32 + qr][0];
#pragma unroll
    for (int c = 0; c < 16; c++) *(float4*)&po[c * 4] = o[c].f;
    __syncthreads();

    float invl = 1.0f / lsum;
#pragma unroll
    for (int c = 0; c < 4; c++) {
        int d = kg * 16 + c * 4;
        float4 s0 = *(const float4*)&Ks[qr][d];
        float4 s1 = *(const float4*)&Ks[32 + qr][d];
        float4 s2 = *(const float4*)&Ks[64 + qr][d];
        float4 s3 = *(const float4*)&Ks[96 + qr][d];
        float4 r4;
        r4.x = (s0.x + s1.x + s2.x + s3.x) * invl;
        r4.y = (s0.y + s1.y + s2.y + s3.y) * invl;
        r4.z = (s0.z + s1.z + s2.z + s3.z) * invl;
        r4.w = (s0.w + s1.w + s2.w + s3.w) * invl;
        *(float4*)&g_attn[base + qi][hc + d] = r4;
    }
}

// =============== refine head, stage A: comb -> ff (2048 rows) ===============
__global__ void __launch_bounds__(256) refineA_kernel(
    const float* __restrict__ Wemb, const float* __restrict__ bemb,
    const float* __restrict__ Wr1, const float* __restrict__ br1,
    int step, int first) {
    int b = blockIdx.x >> 4, part = blockIdx.x & 15;
    __shared__ float comb[1024];
    __shared__ float cur[32];
    int tid = threadIdx.x;
    int ptr = TH + step;
    if (tid < 32) cur[tid] = first ? g_buf[b][ptr - 1][tid] : g_cur[b][tid];
    __syncthreads();
    for (int d = tid; d < 512; d += 256) {
        const float* w = &Wemb[d * 32];
        float s = 0.0f;
#pragma unroll
        for (int i = 0; i < 32; i += 4) {
            float4 wv = *(const float4*)&w[i];
            s += wv.x * cur[i] + wv.y * cur[i + 1] + wv.z * cur[i + 2] + wv.w * cur[i + 3];
        }
        comb[d] = (s + bemb[d]) * EMB_SCALE;
    }
    for (int d = tid; d < 512; d += 256) comb[512 + d] = g_h[b * T + ptr - 1][d];
    __syncthreads();

    int r = part * 128 + (tid >> 1);
    int half = tid & 1;
    const float* w = &Wr1[r * 1024 + half * 512];
    const float* cb = &comb[half * 512];
    u64 a0 = pack2(0.f, 0.f), a1 = pack2(0.f, 0.f);
    for (int i = 0; i < 512; i += 4) {
        F4U wv; wv.f = *(const float4*)&w[i];
        F4U cv; cv.f = *(const float4*)&cb[i];
        fma2(a0, wv.u[0], cv.u[0]);
        fma2(a1, wv.u[1], cv.u[1]);
    }
    float2 x0 = unpack2(a0), x1 = unpack2(a1);
    float s = x0.x + x0.y + x1.x + x1.y;
    s += __shfl_xor_sync(~0u, s, 1);
    if (half == 0) g_ffr[b][r] = gelu(s + br1[r]);
}

// =============== refine head, stage B: delta + cur update ===============
__global__ void __launch_bounds__(256) refineB_kernel(
    const float* __restrict__ Wr2, const float* __restrict__ br2,
    float* __restrict__ out, int step, int first, int last) {
    int b = blockIdx.x;
    int tid = threadIdx.x;
    __shared__ float ff[2048];
    for (int i = tid; i < 2048; i += 256) ff[i] = g_ffr[b][i];
    __syncthreads();
    int i = tid >> 3, part = tid & 7;
    const float* w = &Wr2[i * 2048 + part * 256];
    const float* f = &ff[part * 256];
    u64 a0 = pack2(0.f, 0.f), a1 = pack2(0.f, 0.f);
    for (int j = 0; j < 256; j += 4) {
        F4U wv; wv.f = *(const float4*)&w[j];
        F4U fv; fv.f = *(const float4*)&f[j];
        fma2(a0, wv.u[0], fv.u[0]);
        fma2(a1, wv.u[1], fv.u[1]);
    }
    float2 x0 = unpack2(a0), x1 = unpack2(a1);
    float s = x0.x + x0.y + x1.x + x1.y;
    s += __shfl_xor_sync(~0u, s, 1);
    s += __shfl_xor_sync(~0u, s, 2);
    s += __shfl_xor_sync(~0u, s, 4);
    if (part == 0) {
        int ptr = TH + step;
        float base = first ? g_buf[b][ptr - 1][i] : g_cur[b][i];
        float nv = base + s + br2[i];
        g_cur[b][i] = nv;
        if (last) {
            g_buf[b][ptr][i] = nv;
            out[(b * STEPS + step) * D_IN + i] = nv;
        }
    }
}

// =============== host orchestration ===============
extern "C" void kernel_launch(void* const* d_in, const int* in_sizes, int n_in,
                              void* d_out, int out_size) {
    int o = (n_in >= 20) ? 1 : 0;   // "steps" scalar occupies index 1 if present
    const float* history = (const float*)d_in[0];
    const float* Wemb = (const float*)d_in[1 + o];
    const float* bemb = (const float*)d_in[2 + o];
    const float* Wq = (const float*)d_in[3 + o];
    const float* Wk = (const float*)d_in[4 + o];
    const float* Wv = (const float*)d_in[5 + o];
    const float* Wo = (const float*)d_in[6 + o];
    const float* ln1g = (const float*)d_in[7 + o];
    const float* ln1b = (const float*)d_in[8 + o];
    const float* W1 = (const float*)d_in[9 + o];
    const float* b1 = (const float*)d_in[10 + o];
    const float* W2 = (const float*)d_in[11 + o];
    const float* b2 = (const float*)d_in[12 + o];
    const float* ln2g = (const float*)d_in[13 + o];
    const float* ln2b = (const float*)d_in[14 + o];
    const float* Wr1 = (const float*)d_in[15 + o];
    const float* br1 = (const float*)d_in[16 + o];
    const float* Wr2 = (const float*)d_in[17 + o];
    const float* br2 = (const float*)d_in[18 + o];
    float* out = (float*)d_out;

    void* p;
    cudaGetSymbolAddress(&p, g_h);    float* ph = (float*)p;
    cudaGetSymbolAddress(&p, g_q);    float* pq = (float*)p;
    cudaGetSymbolAddress(&p, g_k);    float* pk = (float*)p;
    cudaGetSymbolAddress(&p, g_v);    float* pv = (float*)p;
    cudaGetSymbolAddress(&p, g_attn); float* pat = (float*)p;
    cudaGetSymbolAddress(&p, g_tmp);  float* ptmp = (float*)p;
    cudaGetSymbolAddress(&p, g_ff);   float* pff = (float*)p;

    init_buf_kernel<<<B, 256>>>(history);

    for (int step = 0; step < STEPS; step++) {
        embed_kernel<<<M, 128>>>(Wemb, bemb);
        for (int l = 0; l < N_LAYERS; l++) {
            const float* wq = Wq + l * D_MODEL * D_MODEL;
            const float* wk = Wk + l * D_MODEL * D_MODEL;
            const float* wv = Wv + l * D_MODEL * D_MODEL;
            const float* wo = Wo + l * D_MODEL * D_MODEL;
            const float* w1 = W1 + l * D_FF * D_MODEL;
            const float* w2 = W2 + l * D_MODEL * D_FF;

            gemm_kernel<64, 32, 0><<<dim3(16, 8, 3), 256>>>(
                ph, wq, wk, wv, pq, pk, pv, nullptr, nullptr, 512, 512);
            attn_kernel<<<dim3(4, 32), 128>>>();
            gemm_kernel<64, 32, 2><<<dim3(16, 8, 1), 256>>>(
                pat, wo, wo, wo, ptmp, ptmp, ptmp, nullptr, ph, 512, 512);
            ln_kernel<<<512, 128>>>(ptmp, ln1g + l * 512, ln1b + l * 512, ph);
            gemm_kernel<128, 64, 1><<<dim3(32, 4, 1), 256>>>(
                ph, w1, w1, w1, pff, pff, pff, b1 + l * D_FF, nullptr, 2048, 512);
            gemm_kernel<64, 32, 3><<<dim3(16, 8, 1), 256>>>(
                pff, w2, w2, w2, ptmp, ptmp, ptmp, b2 + l * 512, ph, 512, 2048);
            ln_kernel<<<512, 128>>>(ptmp, ln2g + l * 512, ln2b + l * 512, ph);
        }
        for (int s = 0; s < N_SUB; s++) {
            refineA_kernel<<<64, 256>>>(Wemb, bemb, Wr1, br1, step, s == 0);
            refineB_kernel<<<4, 256>>>(Wr2, br2, out, step, s == 0, s == N_SUB - 1);
        }
    }
}